// round 4
// baseline (speedup 1.0000x reference)
#include <cuda_runtime.h>
#include <cuda_bf16.h>
#include <utility>

// DefocusBlur: depthwise 17x17 cross-correlation, reflect-101 borders.
// Input:  d_in[0] = float32 [32,3,512,512]; Output same shape.
//
// Issue-bound kernel -> minimize instructions/output:
//  * compile-time weight table -> FFMA immediate form (rt_SMSP=1)
//  * horizontal mirror symmetry: pair sums halve FFMAs per row-dot
//  * vertical mirror symmetry: row-dot d=min(dy,16-dy) shared between two
//    outputs within a 16-output vertical strip
//  * NEW: 2 adjacent pixels per thread; their 17-wide windows overlap in 16
//    columns -> one 18-value window via 9x LDS.64 serves both pixels
//    (LDS instrs 34->9 per output, smem crossbar bytes halved)

struct WTab { float w[17][17]; };

__host__ __device__ constexpr WTab make_wtab() {
    WTab t{};
    const float g0 = 0.10650698f;
    const float g1 = 0.78698604f;
    const float g[3] = {g0, g1, g0};
    for (int i = 0; i < 17; ++i) {
        for (int j = 0; j < 17; ++j) {
            float s = 0.0f;
            for (int a = 0; a < 3; ++a) {
                for (int b = 0; b < 3; ++b) {
                    int r = i + a - 1;
                    int c = j + b - 1;
                    r = (r < 0) ? -r : ((r > 16) ? 32 - r : r);   // reflect-101
                    c = (c < 0) ? -c : ((c > 16) ? 32 - c : c);
                    const int dy = r - 8;
                    const int dx = c - 8;
                    if (dy * dy + dx * dx <= 64) s += g[a] * g[b];
                }
            }
            t.w[i][j] = s / 197.0f;
        }
    }
    // Symmetrize exactly: copy from the canonical quadrant (<=1 ulp change).
    WTab u{};
    for (int i = 0; i < 17; ++i) {
        for (int j = 0; j < 17; ++j) {
            const int ci = (i < 16 - i) ? i : 16 - i;
            const int cj = (j < 16 - j) ? j : 16 - j;
            u.w[i][j] = t.w[ci][cj];
        }
    }
    return u;
}

constexpr WTab WT = make_wtab();

__host__ __device__ constexpr int dmin(int dy) { return (dy < 16 - dy) ? dy : 16 - dy; }

#define KPT 16                      // outputs per thread (vertical strip)
__host__ __device__ constexpr bool needed_rd(int R, int D) {
    for (int k = 0; k < KPT; ++k) {
        const int dy = R - k;
        if (dy >= 0 && dy <= 16 && dmin(dy) == D) return true;
    }
    return false;
}

#define TILE_W 64
#define TILE_H 64
#define HALO   8
#define SMW    (TILE_W + 2 * HALO)   // 80
#define SMH    (TILE_H + 2 * HALO)   // 80
#define NTHREADS 128                 // 32 x-pairs * 4 strips

// ---- one symmetric tap pair: s += w[D][8+J] * p[J] ----
template <int D, int J>
__device__ __forceinline__ void pairtap(float& s, const float* p) {
    constexpr float w = WT.w[D][8 + J];     // == WT.w[D][8-J] by construction
    if constexpr (w != 0.0f) s = fmaf(p[J], w, s);
}

template <int D, int... Js>
__device__ __forceinline__ void pairtaps(float& s, const float* p,
                                         std::integer_sequence<int, Js...>) {
    (pairtap<D, Js + 1>(s, p), ...);
}

// ---- row dot for weight-row D (only if some output of this strip needs it)
template <int R, int D>
__device__ __forceinline__ void calc_dot(float* dot, const float* p) {
    if constexpr (needed_rd(R, D)) {
        float s;
        constexpr float wc = WT.w[D][8];
        if constexpr (wc != 0.0f) s = wc * p[0]; else s = 0.0f;
        pairtaps<D>(s, p, std::make_integer_sequence<int, 8>{});
        dot[D] = s;
    }
}

template <int R, int... Ds>
__device__ __forceinline__ void calc_dots(float* dot, const float* p,
                                          std::integer_sequence<int, Ds...>) {
    (calc_dot<R, Ds>(dot, p), ...);
}

// ---- distribute the shared dots into the strip's accumulators ----
template <int R, int K>
__device__ __forceinline__ void comb1(float* acc, const float* dot) {
    constexpr int dy = R - K;
    if constexpr (dy >= 0 && dy <= 16) acc[K] += dot[dmin(dy)];
}

template <int R, int... Ks>
__device__ __forceinline__ void combine(float* acc, const float* dot,
                                        std::integer_sequence<int, Ks...>) {
    (comb1<R, Ks>(acc, dot), ...);
}

template <int R>
__device__ __forceinline__ void do_row(const float* __restrict__ Srow,
                                       float* acc0, float* acc1) {
    // Srow = &S[rbase + R][2*txp]; 8-byte aligned (SMW even, even column).
    // 18-value window serves both pixels: centers at v[8] and v[9].
    float v[18];
    #pragma unroll
    for (int m = 0; m < 9; ++m) {
        const float2 t = *reinterpret_cast<const float2*>(Srow + 2 * m);  // LDS.64
        v[2 * m]     = t.x;
        v[2 * m + 1] = t.y;
    }
    // ---- pixel 0 ----
    {
        float p[9];
        p[0] = v[8];
        #pragma unroll
        for (int j = 1; j <= 8; ++j) p[j] = v[8 - j] + v[8 + j];
        float dot[9];
        calc_dots<R>(dot, p, std::make_integer_sequence<int, 9>{});
        combine<R>(acc0, dot, std::make_integer_sequence<int, KPT>{});
    }
    // ---- pixel 1 ----
    {
        float p[9];
        p[0] = v[9];
        #pragma unroll
        for (int j = 1; j <= 8; ++j) p[j] = v[9 - j] + v[9 + j];
        float dot[9];
        calc_dots<R>(dot, p, std::make_integer_sequence<int, 9>{});
        combine<R>(acc1, dot, std::make_integer_sequence<int, KPT>{});
    }
}

template <int... Rs>
__device__ __forceinline__ void all_rows(const float* __restrict__ Sbase,
                                         float* acc0, float* acc1,
                                         std::integer_sequence<int, Rs...>) {
    (do_row<Rs>(Sbase + Rs * SMW, acc0, acc1), ...);
}

__global__ void __launch_bounds__(NTHREADS)
defocus_blur_kernel(const float* __restrict__ in, float* __restrict__ out) {
    __shared__ float S[SMH][SMW];

    const int plane = blockIdx.z;                 // 0..95
    const int X0 = blockIdx.x * TILE_W;
    const int Y0 = blockIdx.y * TILE_H;

    const float* __restrict__ ip = in  + (size_t)plane * 512 * 512;
    float* __restrict__       op = out + (size_t)plane * 512 * 512;

    // ---- cooperative tile load, reflect-101 borders (6400 elems, 50/thread)
    float* Sf = &S[0][0];
    #pragma unroll
    for (int idx = threadIdx.x; idx < SMH * SMW; idx += NTHREADS) {
        const int ly = idx / SMW;
        const int lx = idx - ly * SMW;
        int gy = Y0 - HALO + ly;
        gy = (gy < 0) ? -gy : ((gy > 511) ? 1022 - gy : gy);
        int gx = X0 - HALO + lx;
        gx = (gx < 0) ? -gx : ((gx > 511) ? 1022 - gx : gx);
        Sf[idx] = __ldg(&ip[gy * 512 + gx]);
    }
    __syncthreads();

    const int txp = threadIdx.x & 31;    // x-pair index (2 pixels each)
    const int ty  = threadIdx.x >> 5;    // which 16-row output strip (0..3)

    float acc0[KPT], acc1[KPT];
    #pragma unroll
    for (int k = 0; k < KPT; ++k) { acc0[k] = 0.0f; acc1[k] = 0.0f; }

    // Strip covers input rows [ty*16, ty*16+31] of the padded tile.
    all_rows(&S[ty * KPT][2 * txp], acc0, acc1,
             std::make_integer_sequence<int, KPT + 16>{});

    // ---- store 16 output rows, 2 pixels per thread -> STG.64 ----
    const int yo = Y0 + ty * KPT;
    const int xo = X0 + 2 * txp;
    #pragma unroll
    for (int k = 0; k < KPT; ++k) {
        float2 o; o.x = acc0[k]; o.y = acc1[k];
        *reinterpret_cast<float2*>(&op[(yo + k) * 512 + xo]) = o;
    }
}

extern "C" void kernel_launch(void* const* d_in, const int* in_sizes, int n_in,
                              void* d_out, int out_size) {
    const float* in = (const float*)d_in[0];
    float* out = (float*)d_out;
    dim3 grid(512 / TILE_W, 512 / TILE_H, 96);   // 8 x 8 x 96 = 6144 blocks
    defocus_blur_kernel<<<grid, NTHREADS>>>(in, out);
}

// round 5
// speedup vs baseline: 1.0336x; 1.0336x over previous
#include <cuda_runtime.h>
#include <cuda_bf16.h>
#include <utility>

// DefocusBlur: depthwise 17x17 cross-correlation, reflect-101 borders.
// Input:  d_in[0] = float32 [32,3,512,512]; Output same shape.
//
// Issue-bound kernel -> minimize instructions/output:
//  * compile-time weight table -> FFMA immediate operands (rt_SMSP=1)
//  * horizontal mirror symmetry: pair sums p[j]=v[8-j]+v[8+j]
//  * vertical mirror symmetry: row-dot D=min(dy,16-dy) shared between two
//    outputs within a 16-output vertical strip
//  * NEW: constant-interior box decomposition. The blurred disk equals
//    c = w[8][8] over its whole interior, so per weight-row D:
//      dot_D = c*B[m_int(D)] + sum_{j>m_int} w[D][8+j]*p[j]
//    with B[m] = v8 + sum_{j<=m} p[j] (cumulative, 6 FADDs/row).
//    Cuts row-dot FFMAs ~73 -> ~39 per 9-dot set.

struct WTab { float w[17][17]; };

__host__ __device__ constexpr WTab make_wtab() {
    WTab t{};
    const float g0 = 0.10650698f;
    const float g1 = 0.78698604f;
    const float g[3] = {g0, g1, g0};
    for (int i = 0; i < 17; ++i) {
        for (int j = 0; j < 17; ++j) {
            float s = 0.0f;
            for (int a = 0; a < 3; ++a) {
                for (int b = 0; b < 3; ++b) {
                    int r = i + a - 1;
                    int c = j + b - 1;
                    r = (r < 0) ? -r : ((r > 16) ? 32 - r : r);   // reflect-101
                    c = (c < 0) ? -c : ((c > 16) ? 32 - c : c);
                    const int dy = r - 8;
                    const int dx = c - 8;
                    if (dy * dy + dx * dx <= 64) s += g[a] * g[b];
                }
            }
            t.w[i][j] = s / 197.0f;
        }
    }
    // Symmetrize exactly: copy from the canonical quadrant (<=1 ulp change).
    WTab u{};
    for (int i = 0; i < 17; ++i) {
        for (int j = 0; j < 17; ++j) {
            const int ci = (i < 16 - i) ? i : 16 - i;
            const int cj = (j < 16 - j) ? j : 16 - j;
            u.w[i][j] = t.w[ci][cj];
        }
    }
    return u;
}

constexpr WTab WT = make_wtab();
constexpr float CW = WT.w[8][8];   // interior constant (bit-exact for all
                                   // fully-interior cells: identical fp sum)

__host__ __device__ constexpr int dmin(int dy) { return (dy < 16 - dy) ? dy : 16 - dy; }

#define KPT 16                      // outputs per thread (vertical strip)
__host__ __device__ constexpr bool needed_rd(int R, int D) {
    for (int k = 0; k < KPT; ++k) {
        const int dy = R - k;
        if (dy >= 0 && dy <= 16 && dmin(dy) == D) return true;
    }
    return false;
}

// Largest M such that w[D][8+j] == CW for all j <= M (-1 if none).
__host__ __device__ constexpr int m_int(int D) {
    int m = -1;
    for (int j = 0; j <= 8; ++j) {
        if (WT.w[D][8 + j] == CW) m = j;
        else break;
    }
    return m;
}

// Highest B index any needed dot of row R wants (-1 if none).
__host__ __device__ constexpr int maxM(int R) {
    int mm = -1;
    for (int D = 0; D <= 8; ++D) {
        if (needed_rd(R, D)) {
            const int m = m_int(D);
            if (m > mm) mm = m;
        }
    }
    return mm;
}

#define TILE_W 64
#define TILE_H 64
#define HALO   8
#define SMW    (TILE_W + 2 * HALO)   // 80
#define SMH    (TILE_H + 2 * HALO)   // 80
#define NTHREADS 256

// ---- correction taps: only j beyond the constant interior ----
template <int D, int M, int J>
__device__ __forceinline__ void corrtap(float& s, const float* p) {
    if constexpr (J > M) {
        constexpr float w = WT.w[D][8 + J];
        if constexpr (w != 0.0f) s = fmaf(p[J], w, s);
    }
}

template <int D, int M, int... Js>
__device__ __forceinline__ void corrtaps(float& s, const float* p,
                                         std::integer_sequence<int, Js...>) {
    (corrtap<D, M, Js>(s, p), ...);
}

// ---- row dot for weight-row D via box + corrections ----
template <int R, int D>
__device__ __forceinline__ void calc_dot(float* dot, const float* p, const float* B) {
    if constexpr (needed_rd(R, D)) {
        constexpr int M = m_int(D);
        float s;
        if constexpr (M >= 0) s = CW * B[M];
        else                  s = 0.0f;
        corrtaps<D, M>(s, p, std::make_integer_sequence<int, 9>{});
        dot[D] = s;
    }
}

template <int R, int... Ds>
__device__ __forceinline__ void calc_dots(float* dot, const float* p, const float* B,
                                          std::integer_sequence<int, Ds...>) {
    (calc_dot<R, Ds>(dot, p, B), ...);
}

// ---- distribute the shared dots into the strip's accumulators ----
template <int R, int K>
__device__ __forceinline__ void comb1(float* acc, const float* dot) {
    constexpr int dy = R - K;
    if constexpr (dy >= 0 && dy <= 16) acc[K] += dot[dmin(dy)];
}

template <int R, int... Ks>
__device__ __forceinline__ void combine(float* acc, const float* dot,
                                        std::integer_sequence<int, Ks...>) {
    (comb1<R, Ks>(acc, dot), ...);
}

template <int R>
__device__ __forceinline__ void do_row(const float* __restrict__ Srow, float* acc) {
    float v[17];
    #pragma unroll
    for (int j = 0; j < 17; ++j) v[j] = Srow[j];    // LDS with imm offsets
    float p[9];
    p[0] = v[8];
    #pragma unroll
    for (int j = 1; j <= 8; ++j) p[j] = v[8 - j] + v[8 + j];

    constexpr int MB = maxM(R);          // box chain only as deep as needed
    float B[7];
    if constexpr (MB >= 0) {
        B[0] = p[0];
        #pragma unroll
        for (int m = 1; m <= MB; ++m) B[m] = B[m - 1] + p[m];
    }

    float dot[9];
    calc_dots<R>(dot, p, B, std::make_integer_sequence<int, 9>{});
    combine<R>(acc, dot, std::make_integer_sequence<int, KPT>{});
}

template <int... Rs>
__device__ __forceinline__ void all_rows(const float* __restrict__ Sbase,
                                         float* acc,
                                         std::integer_sequence<int, Rs...>) {
    (do_row<Rs>(Sbase + Rs * SMW, acc), ...);
}

__global__ void __launch_bounds__(NTHREADS)
defocus_blur_kernel(const float* __restrict__ in, float* __restrict__ out) {
    __shared__ float S[SMH][SMW];

    const int plane = blockIdx.z;                 // 0..95
    const int X0 = blockIdx.x * TILE_W;
    const int Y0 = blockIdx.y * TILE_H;

    const float* __restrict__ ip = in  + (size_t)plane * 512 * 512;
    float* __restrict__       op = out + (size_t)plane * 512 * 512;

    // ---- cooperative tile load, reflect-101 borders (6400 elems) ----
    float* Sf = &S[0][0];
    #pragma unroll
    for (int idx = threadIdx.x; idx < SMH * SMW; idx += NTHREADS) {
        const int ly = idx / SMW;
        const int lx = idx - ly * SMW;
        int gy = Y0 - HALO + ly;
        gy = (gy < 0) ? -gy : ((gy > 511) ? 1022 - gy : gy);
        int gx = X0 - HALO + lx;
        gx = (gx < 0) ? -gx : ((gx > 511) ? 1022 - gx : gx);
        Sf[idx] = __ldg(&ip[gy * 512 + gx]);
    }
    __syncthreads();

    const int tx = threadIdx.x & 63;     // x within tile
    const int ty = threadIdx.x >> 6;     // which 16-row output strip (0..3)

    float acc[KPT];
    #pragma unroll
    for (int k = 0; k < KPT; ++k) acc[k] = 0.0f;

    // Strip covers input rows [ty*16, ty*16+31] of the padded tile.
    all_rows(&S[ty * KPT][tx], acc, std::make_integer_sequence<int, KPT + 16>{});

    // ---- store 16 output rows, coalesced 64-wide ----
    const int yo = Y0 + ty * KPT;
    #pragma unroll
    for (int k = 0; k < KPT; ++k) {
        op[(yo + k) * 512 + X0 + tx] = acc[k];
    }
}

extern "C" void kernel_launch(void* const* d_in, const int* in_sizes, int n_in,
                              void* d_out, int out_size) {
    const float* in = (const float*)d_in[0];
    float* out = (float*)d_out;
    dim3 grid(512 / TILE_W, 512 / TILE_H, 96);   // 8 x 8 x 96 = 6144 blocks
    defocus_blur_kernel<<<grid, NTHREADS>>>(in, out);
}

// round 6
// speedup vs baseline: 1.1114x; 1.0753x over previous
#include <cuda_runtime.h>
#include <cuda_bf16.h>
#include <utility>

// DefocusBlur: depthwise 17x17 cross-correlation, reflect-101 borders.
// Input:  d_in[0] = float32 [32,3,512,512]; Output same shape.
//
// Issue-slot-bound -> halve slots with Blackwell packed f32x2 math:
//  * tile stored TRANSPOSED in smem (S[x][y], padded stride) so two
//    vertically adjacent rows load as ONE aligned ld.shared.b64
//  * pair sums / row-dots computed for both rows at once via
//    add.rn.f32x2 / fma.rn.f32x2 (1 issue slot = 2 fp32 ops)
//  * weights are compile-time constants, broadcast-packed {w,w}
//  * vertical dot-sharing (dmin) + horizontal pair symmetry retained
//  * combine kept scalar: dot halves are plain registers after mov.b64

using u64 = unsigned long long;

struct WTab { float w[17][17]; };

__host__ __device__ constexpr WTab make_wtab() {
    WTab t{};
    const float g0 = 0.10650698f;
    const float g1 = 0.78698604f;
    const float g[3] = {g0, g1, g0};
    for (int i = 0; i < 17; ++i) {
        for (int j = 0; j < 17; ++j) {
            float s = 0.0f;
            for (int a = 0; a < 3; ++a) {
                for (int b = 0; b < 3; ++b) {
                    int r = i + a - 1;
                    int c = j + b - 1;
                    r = (r < 0) ? -r : ((r > 16) ? 32 - r : r);   // reflect-101
                    c = (c < 0) ? -c : ((c > 16) ? 32 - c : c);
                    const int dy = r - 8;
                    const int dx = c - 8;
                    if (dy * dy + dx * dx <= 64) s += g[a] * g[b];
                }
            }
            t.w[i][j] = s / 197.0f;
        }
    }
    WTab u{};   // symmetrize exactly (canonical quadrant copy)
    for (int i = 0; i < 17; ++i)
        for (int j = 0; j < 17; ++j) {
            const int ci = (i < 16 - i) ? i : 16 - i;
            const int cj = (j < 16 - j) ? j : 16 - j;
            u.w[i][j] = t.w[ci][cj];
        }
    return u;
}

constexpr WTab WT = make_wtab();

__host__ __device__ constexpr int dmin(int dy) { return (dy < 16 - dy) ? dy : 16 - dy; }

#define KPT    16
#define TILE_W 64
#define TILE_H 32
#define HALO   8
#define SMW    80          // columns incl halo
#define SMH    48          // rows incl halo
#define SMHP   50          // padded column stride: even (8B align), 25 odd -> no LDS.64 conflicts
#define NTHREADS 128       // 64 columns x 2 strips

// Does row-pair M (local rows 2M, 2M+1) need weight-row D?
__host__ __device__ constexpr bool needD(int M, int D) {
    for (int dy = 0; dy <= 16; ++dy) {
        if (dmin(dy) != D) continue;
        const int kl = 2 * M - dy, kh = 2 * M + 1 - dy;
        if ((kl >= 0 && kl < KPT) || (kh >= 0 && kh < KPT)) return true;
    }
    return false;
}
__host__ __device__ constexpr int jfirst(int D) {
    for (int j = 0; j <= 8; ++j) if (WT.w[D][8 + j] != 0.0f) return j;
    return 9;
}

// ---- packed f32x2 primitives (sm_100a) ----
__device__ __forceinline__ u64 add2(u64 a, u64 b) {
    u64 d; asm("add.rn.f32x2 %0,%1,%2;" : "=l"(d) : "l"(a), "l"(b)); return d;
}
__device__ __forceinline__ u64 mul2(u64 a, u64 b) {
    u64 d; asm("mul.rn.f32x2 %0,%1,%2;" : "=l"(d) : "l"(a), "l"(b)); return d;
}
__device__ __forceinline__ u64 fma2(u64 a, u64 b, u64 c) {
    u64 d; asm("fma.rn.f32x2 %0,%1,%2,%3;" : "=l"(d) : "l"(a), "l"(b), "l"(c)); return d;
}
__device__ __forceinline__ u64 wpack(float w) {
    u64 r; asm("mov.b64 %0,{%1,%1};" : "=l"(r) : "f"(w)); return r;
}
__device__ __forceinline__ void unpack2(u64 v, float& lo, float& hi) {
    asm("mov.b64 {%0,%1},%2;" : "=f"(lo), "=f"(hi) : "l"(v));
}

// ---- dot taps (packed, weight broadcast) ----
template <int D, int J>
__device__ __forceinline__ void dtap(u64& s2, const u64* p2) {
    if constexpr (J > jfirst(D)) {
        constexpr float w = WT.w[D][8 + J];
        if constexpr (w != 0.0f) s2 = fma2(p2[J], wpack(w), s2);
    }
}
template <int D, int... Js>
__device__ __forceinline__ void dtaps(u64& s2, const u64* p2,
                                      std::integer_sequence<int, Js...>) {
    (dtap<D, Js>(s2, p2), ...);
}

// ---- scatter one dot's two halves into the scalar accumulators ----
template <int M, int D, int DY>
__device__ __forceinline__ void scat1(float* acc, float lo, float hi) {
    if constexpr (dmin(DY) == D) {
        constexpr int kl = 2 * M - DY;
        constexpr int kh = 2 * M + 1 - DY;
        if constexpr (kl >= 0 && kl < KPT) acc[kl] += lo;
        if constexpr (kh >= 0 && kh < KPT) acc[kh] += hi;
    }
}
template <int M, int D, int... DYs>
__device__ __forceinline__ void scat(float* acc, float lo, float hi,
                                     std::integer_sequence<int, DYs...>) {
    (scat1<M, D, DYs>(acc, lo, hi), ...);
}

template <int M, int D>
__device__ __forceinline__ void dodot(const u64* p2, float* acc) {
    if constexpr (needD(M, D)) {
        constexpr int JF = jfirst(D);
        u64 s2 = mul2(p2[JF], wpack(WT.w[D][8 + JF]));
        dtaps<D>(s2, p2, std::make_integer_sequence<int, 9>{});
        float lo, hi;
        unpack2(s2, lo, hi);
        scat<M, D>(acc, lo, hi, std::make_integer_sequence<int, 17>{});
    }
}
template <int M, int... Ds>
__device__ __forceinline__ void dodots(const u64* p2, float* acc,
                                       std::integer_sequence<int, Ds...>) {
    (dodot<M, Ds>(p2, acc), ...);
}

// ---- one row-pair: 17 LDS.64 + 8 ADD2 + packed dots + scalar scatter ----
template <int M>
__device__ __forceinline__ void rowpair(const float* __restrict__ colbase, float* acc) {
    // colbase = &S[tx * SMHP + rbase]; column dx at +dx*SMHP, rows 2M,2M+1 at +2M.
    u64 p2[9];
    p2[0] = *reinterpret_cast<const u64*>(colbase + 8 * SMHP + 2 * M);
    #pragma unroll
    for (int j = 1; j <= 8; ++j) {
        const u64 a = *reinterpret_cast<const u64*>(colbase + (8 - j) * SMHP + 2 * M);
        const u64 b = *reinterpret_cast<const u64*>(colbase + (8 + j) * SMHP + 2 * M);
        p2[j] = add2(a, b);
    }
    dodots<M>(p2, acc, std::make_integer_sequence<int, 9>{});
}

template <int... Ms>
__device__ __forceinline__ void rowpairs(const float* __restrict__ colbase, float* acc,
                                         std::integer_sequence<int, Ms...>) {
    (rowpair<Ms>(colbase, acc), ...);
}

__global__ void __launch_bounds__(NTHREADS, 10)
defocus_blur_kernel(const float* __restrict__ in, float* __restrict__ out) {
    __shared__ float S[SMW * SMHP];    // TRANSPOSED: S[x*SMHP + y]

    const int plane = blockIdx.z;                 // 0..95
    const int X0 = blockIdx.x * TILE_W;
    const int Y0 = blockIdx.y * TILE_H;

    const float* __restrict__ ip = in  + (size_t)plane * 512 * 512;
    float* __restrict__       op = out + (size_t)plane * 512 * 512;

    // ---- cooperative transposed tile load, reflect-101 (3840 elems) ----
    #pragma unroll
    for (int idx = threadIdx.x; idx < SMH * SMW; idx += NTHREADS) {
        const int ly = idx / SMW;          // row    (gmem-coalesced in lx)
        const int lx = idx - ly * SMW;     // column
        int gy = Y0 - HALO + ly;
        gy = (gy < 0) ? -gy : ((gy > 511) ? 1022 - gy : gy);
        int gx = X0 - HALO + lx;
        gx = (gx < 0) ? -gx : ((gx > 511) ? 1022 - gx : gx);
        S[lx * SMHP + ly] = __ldg(&ip[gy * 512 + gx]);
    }
    __syncthreads();

    const int tx = threadIdx.x & 63;     // output column within tile
    const int ty = threadIdx.x >> 6;     // strip (0..1), KPT outputs each

    float acc[KPT];
    #pragma unroll
    for (int k = 0; k < KPT; ++k) acc[k] = 0.0f;

    // Strip covers padded rows [ty*16, ty*16+31] = 16 row-pairs.
    const float* colbase = &S[tx * SMHP + ty * KPT];
    rowpairs(colbase, acc, std::make_integer_sequence<int, 16>{});

    // ---- store 16 output rows, coalesced 64-wide ----
    const int yo = Y0 + ty * KPT;
    #pragma unroll
    for (int k = 0; k < KPT; ++k) {
        op[(yo + k) * 512 + X0 + tx] = acc[k];
    }
}

extern "C" void kernel_launch(void* const* d_in, const int* in_sizes, int n_in,
                              void* d_out, int out_size) {
    const float* in = (const float*)d_in[0];
    float* out = (float*)d_out;
    dim3 grid(512 / TILE_W, 512 / TILE_H, 96);   // 8 x 16 x 96 = 12288 blocks
    defocus_blur_kernel<<<grid, NTHREADS>>>(in, out);
}